// round 16
// baseline (speedup 1.0000x reference)
#include <cuda_runtime.h>
#include <cuda_fp16.h>
#include <cstdint>

// ---------------- problem constants ----------------
#define FEA      64
#define NTOT     14112
#define COST_IDX (NTOT * FEA)               /* 903168 */
#define INV_CNT  (1.0f / (14112.0f * 4096.0f))
#define LOG2E    1.4426950408889634f

// W b-fragments, fp16x2 (single-term fp16 GEMM).
// Flat u32 index t = ((i*4 + ks)*32 + lane)*4 + w  (i,ks<4, lane<32, w<4):
// the 4 uint4 loads per (ks,lane) are lane-consecutive -> coalesced.
// Word (i,w): idx16 = i*4+w = nt*2+r. K-PERMUTED to match float4 A loads:
//   k_orig = 16*ks + 4*(lane&3) + 2*r + {0,1}
__device__ unsigned g_Bfh[2048];

// ---------------- helpers ----------------
__device__ __forceinline__ uint32_t packh2(float x, float y) {
    __half2 hh = __floats2half2_rn(x, y);
    return *(uint32_t*)&hh;
}

__device__ __forceinline__ float ex2f(float a) {
    float r;
    asm("ex2.approx.f32 %0, %1;" : "=f"(r) : "f"(a));
    return r;
}

#define MMA_F16(d, a, b) \
    asm volatile("mma.sync.aligned.m16n8k16.row.col.f32.f16.f16.f32 " \
                 "{%0,%1,%2,%3},{%4,%5,%6,%7},{%8,%9},{%0,%1,%2,%3};" \
                 : "+f"((d)[0]), "+f"((d)[1]), "+f"((d)[2]), "+f"((d)[3]) \
                 : "r"((a)[0]), "r"((a)[1]), "r"((a)[2]), "r"((a)[3]), \
                   "r"((b)[0]), "r"((b)[1]))

// ---------------- prep: W -> fp16 b-frag table, zero cost slot -------------
__global__ void ot_prep_kernel(const float* __restrict__ W,
                               float* __restrict__ out, int out_size) {
    int t = blockIdx.x * blockDim.x + threadIdx.x;   // 0..2047
    if (t < 2048) {
        int w    = t & 3;
        int lane = (t >> 2) & 31;
        int ks   = (t >> 7) & 3;
        int i    = t >> 9;
        int idx16 = i * 4 + w;        // nt*2 + r
        int nt   = idx16 >> 1;
        int r    = idx16 & 1;
        int nn   = (lane >> 2) + 8 * nt;                       // B col (output h)
        int k    = 16 * ks + ((lane & 3) << 2) + (r << 1);     // permuted k
        __half2 hh = __floats2half2_rn(W[nn * 64 + k], W[nn * 64 + k + 1]);
        g_Bfh[t] = *(uint32_t*)&hh;
    }
    if (t == 0)
        for (int i = COST_IDX; i < out_size; ++i) out[i] = 0.0f;
}

// ---------------- main kernel: 1 CTA / problem, register-resident ----------
__global__ void __launch_bounds__(128, 8)
ot_mma_kernel(const float* __restrict__ x, const float* __restrict__ P,
              const float* __restrict__ mask, const float* __restrict__ bias,
              const float* __restrict__ gamma, const float* __restrict__ beta,
              float* __restrict__ out, int out_size) {

    __shared__ float spar[4][64];        // [0]=bias [1]=gamma' [2]=beta' [3]=mask
    __shared__ float txbuf[4][64];
    __shared__ float cred[4];

    const int n    = blockIdx.x;
    const int tid  = threadIdx.x;
    const int lane = tid & 31;
    const int wid  = tid >> 5;
    const int q    = lane >> 2;          // group id 0..7
    const int tg   = lane & 3;           // thread-in-group
    const int c2   = tg << 1;            // col pair base

    // n -> (b, v, p); x/out row base (32-bit offsets — all fit)
    const int bb = n / (21 * 42);
    const int rm = n - bb * (21 * 42);
    const int vv = rm / 42;
    const int pp = rm - vv * 42;
    const int xob = ((bb * 42 + pp) * 21 + vv) * FEA;

    const int fA = 16 * wid + q;         // this thread's two M rows
    const int fB = fA + 8;

    // ---- stage params + mask into smem (one warp per array) ----
    {
        if (wid == 0) {
            ((float2*)spar[0])[lane] = ((const float2*)bias)[lane];
        } else if (wid == 1) {
            float2 v = ((const float2*)gamma)[lane];
            v.x *= LOG2E; v.y *= LOG2E;
            ((float2*)spar[1])[lane] = v;
        } else if (wid == 2) {
            float2 v = ((const float2*)beta)[lane];
            v.x *= LOG2E; v.y *= LOG2E;
            ((float2*)spar[2])[lane] = v;
        } else {
            ((float2*)spar[3])[lane] = ((const float2*)(mask + (n << 6)))[lane];
        }
    }

    // ---- hoisted x row values ----
    const float xfA = x[xob + fA];
    const float xfB = x[xob + fB];

    // ---- A fragments: one float4 per row per 16-k chunk (permuted k),
    //      packed straight into MMA operand order {A.lo, B.lo, A.hi, B.hi} ----
    const float4* P4 = (const float4*)P + ((unsigned)n << 10);
    uint32_t aop[4][4];
    {
        const int baseA = fA * 16 + tg;
        const int baseB = fB * 16 + tg;
#pragma unroll
        for (int j = 0; j < 4; ++j) {
            float4 ua = P4[baseA + 4 * j];
            float4 ub = P4[baseB + 4 * j];
            aop[j][0] = packh2(ua.x, ua.y);
            aop[j][1] = packh2(ub.x, ub.y);
            aop[j][2] = packh2(ua.z, ua.w);
            aop[j][3] = packh2(ub.z, ub.w);
        }
    }
    __syncthreads();     // param smem ready (fill latency hidden under A loads)

    // ---- GEMM: 32 HMMA, B streamed in 8-word halves (low reg pressure) ----
    float acc[8][4];
#pragma unroll
    for (int nt = 0; nt < 8; ++nt)
#pragma unroll
        for (int j = 0; j < 4; ++j) acc[nt][j] = 0.f;

#pragma unroll
    for (int ks = 0; ks < 4; ++ks) {
#pragma unroll
        for (int h = 0; h < 2; ++h) {    // half: i = 2h, 2h+1 -> nt 4h..4h+3
            uint32_t bw[8];
#pragma unroll
            for (int i2 = 0; i2 < 2; ++i2) {
                uint4 v = ((const uint4*)g_Bfh)[((2 * h + i2) * 4 + ks) * 32 + lane];
                bw[4*i2 + 0] = v.x;
                bw[4*i2 + 1] = v.y;
                bw[4*i2 + 2] = v.z;
                bw[4*i2 + 3] = v.w;
            }
#pragma unroll
            for (int j2 = 0; j2 < 4; ++j2) {
                int nt = 4 * h + j2;
                MMA_F16(acc[nt], aop[ks], (&bw[2 * j2]));
            }
        }
    }

    // ---- bias + LN stats (bias via smem broadcast LDS) ----
    const float2* bs2 = (const float2*)spar[0];
    float vA[16], vB[16];
    float s1A = 0.f, s2A = 0.f, s1B = 0.f, s2B = 0.f;
#pragma unroll
    for (int nt = 0; nt < 8; ++nt) {
        float2 bv = bs2[4 * nt + tg];
        float a0 = acc[nt][0] + bv.x;
        float a1 = acc[nt][1] + bv.y;
        float b0 = acc[nt][2] + bv.x;
        float b1 = acc[nt][3] + bv.y;
        vA[2*nt] = a0; vA[2*nt+1] = a1;
        vB[2*nt] = b0; vB[2*nt+1] = b1;
        s1A += a0 + a1; s2A += a0*a0 + a1*a1;
        s1B += b0 + b1; s2B += b0*b0 + b1*b1;
    }
#pragma unroll
    for (int m = 1; m <= 2; m <<= 1) {
        s1A += __shfl_xor_sync(0xffffffffu, s1A, m);
        s2A += __shfl_xor_sync(0xffffffffu, s2A, m);
        s1B += __shfl_xor_sync(0xffffffffu, s1B, m);
        s2B += __shfl_xor_sync(0xffffffffu, s2B, m);
    }
    const float muA = s1A * (1.0f/64.0f);
    const float muB = s1B * (1.0f/64.0f);
    const float rsA = rsqrtf(s2A * (1.0f/64.0f) - muA*muA + 1e-5f);
    const float rsB = rsqrtf(s2B * (1.0f/64.0f) - muB*muB + 1e-5f);
    const float nmrA = -muA * rsA;       // t = v*rs + nmr
    const float nmrB = -muB * rsB;

    // ---- LN affine + exp: FFMA + FFMA + EX2 (log2e folded into gamma'/beta')
    // No max subtraction: |t| <= 8 so exp(z) <= ~e^8, safe in fp32;
    // softmax is shift-invariant -> identical result.
    const float2* gs2 = (const float2*)spar[1];
    const float2* es2 = (const float2*)spar[2];
    float sA = 0.f, sB = 0.f;
#pragma unroll
    for (int nt = 0; nt < 8; ++nt) {
        float2 gv = gs2[4 * nt + tg];
        float2 ev = es2[4 * nt + tg];
        float tA0 = fmaf(vA[2*nt],   rsA, nmrA);
        float tA1 = fmaf(vA[2*nt+1], rsA, nmrA);
        float tB0 = fmaf(vB[2*nt],   rsB, nmrB);
        float tB1 = fmaf(vB[2*nt+1], rsB, nmrB);
        float eA0 = ex2f(fmaf(tA0, gv.x, ev.x));
        float eA1 = ex2f(fmaf(tA1, gv.y, ev.y));
        float eB0 = ex2f(fmaf(tB0, gv.x, ev.x));
        float eB1 = ex2f(fmaf(tB1, gv.y, ev.y));
        vA[2*nt] = eA0; vA[2*nt+1] = eA1;
        vB[2*nt] = eB0; vB[2*nt+1] = eB1;
        sA += eA0 + eA1; sB += eB0 + eB1;
    }
#pragma unroll
    for (int m = 1; m <= 2; m <<= 1) {
        sA += __shfl_xor_sync(0xffffffffu, sA, m);
        sB += __shfl_xor_sync(0xffffffffu, sB, m);
    }
    const float invA = __fdividef(1.0f, sA);
    const float invB = __fdividef(1.0f, sB);
    const float sclA = xfA * invA;       // transport scale, normalization folded
    const float sclB = xfB * invB;

    // ---- cost dot (unnormalized, mask via smem LDS) + transport partials ----
    const float2* ms2s = (const float2*)spar[3];
    float dotA = 0.f, dotB = 0.f;
    float t[16];
#pragma unroll
    for (int nt = 0; nt < 8; ++nt) {
        float2 mv = ms2s[4 * nt + tg];
        dotA = fmaf(vA[2*nt], mv.x, fmaf(vA[2*nt+1], mv.y, dotA));
        dotB = fmaf(vB[2*nt], mv.x, fmaf(vB[2*nt+1], mv.y, dotB));
        t[2*nt]   = fmaf(vA[2*nt],   sclA, vB[2*nt]   * sclB);
        t[2*nt+1] = fmaf(vA[2*nt+1], sclA, vB[2*nt+1] * sclB);
    }
    float costp = fmaf(dotA, invA, dotB * invB);

    // ---- transport: reduce-scatter over the 8 quads (14 shuffles) ----
    // final owner: thread (q,tg) holds cols 8q+2tg, 8q+2tg+1
    {
        const bool hi4 = (q & 4) != 0;
        float u[8];
#pragma unroll
        for (int j = 0; j < 8; ++j) {
            float send = hi4 ? t[j] : t[8 + j];
            float recv = __shfl_xor_sync(0xffffffffu, send, 16);
            u[j] = (hi4 ? t[8 + j] : t[j]) + recv;
        }
        const bool hi2 = (q & 2) != 0;
        float v[4];
#pragma unroll
        for (int j = 0; j < 4; ++j) {
            float send = hi2 ? u[j] : u[4 + j];
            float recv = __shfl_xor_sync(0xffffffffu, send, 8);
            v[j] = (hi2 ? u[4 + j] : u[j]) + recv;
        }
        const bool hi1 = (q & 1) != 0;
        float s0 = hi1 ? v[0] : v[2];
        float r0 = __shfl_xor_sync(0xffffffffu, s0, 4);
        float w0 = (hi1 ? v[2] : v[0]) + r0;
        float s1 = hi1 ? v[1] : v[3];
        float r1 = __shfl_xor_sync(0xffffffffu, s1, 4);
        float w1 = (hi1 ? v[3] : v[1]) + r1;
        *(float2*)&txbuf[wid][8 * q + c2] = make_float2(w0, w1);
    }

    // ---- cost warp reduce ----
#pragma unroll
    for (int m = 1; m <= 16; m <<= 1)
        costp += __shfl_xor_sync(0xffffffffu, costp, m);
    if (lane == 0) cred[wid] = costp;
    __syncthreads();

    // ---- combine warps: output row + cost atomic ----
    if (tid < FEA)
        out[xob + tid] = (txbuf[0][tid] + txbuf[1][tid])
                       + (txbuf[2][tid] + txbuf[3][tid]);
    if (tid == 0 && out_size > COST_IDX)
        atomicAdd(&out[COST_IDX], (cred[0] + cred[1] + cred[2] + cred[3]) * INV_CNT);
}

extern "C" void kernel_launch(void* const* d_in, const int* in_sizes, int n_in,
                              void* d_out, int out_size) {
    const float* x     = (const float*)d_in[0];
    const float* P     = (const float*)d_in[1];
    const float* mask  = (const float*)d_in[2];
    const float* W     = (const float*)d_in[3];
    const float* bias  = (const float*)d_in[4];
    const float* gamma = (const float*)d_in[5];
    const float* beta  = (const float*)d_in[6];
    float* out = (float*)d_out;

    ot_prep_kernel<<<8, 256>>>(W, out, out_size);
    ot_mma_kernel<<<NTOT, 128>>>(x, P, mask, bias, gamma, beta, out, out_size);
}